// round 16
// baseline (speedup 1.0000x reference)
#include <cuda_runtime.h>
#include <cuda_fp16.h>
#include <cstdint>

// ---------------- problem constants ----------------
#define M_TOTAL   14400      // 16 * 30 * 30
#define N_TOTAL   512
#define K_TOTAL   1152
#define OHW       900        // 30*30
#define XSTRIDE_N 262144     // 256*32*32
#define OSTRIDE_N 460800     // 512*900

#define BK 32
#define NCHUNK   36          // K_TOTAL / BK
#define NSTEPS   72          // 2 ks-steps per chunk
#define MTILES   113         // prep A granularity stays 128 rows
#define M64TILES 225         // 14400 / 64 exactly
#define NBLKS    8           // N_TOTAL / 64
#define PTHREADS 256
#define NTHREADS 128

__device__ uint4 g_ah[NCHUNK * MTILES * 512];   // ~33.3 MB, per-thread A fragments
__device__ uint4 g_bh[NCHUNK * NBLKS * 256];    // ~1.2 MB,  B fragments (uint4-packed)

// pack two floats into f16x2 word: lo = a, hi = b
__device__ __forceinline__ uint32_t h2(float a, float b) {
    uint32_t r;
    asm("cvt.rn.f16x2.f32 %0, %1, %2;" : "=r"(r) : "f"(b), "f"(a));
    return r;
}

// ---------------- fused prep: A gather (by<113) or B pack (by>=113) ----------------
// A tile (chunk c, mtile bmt): 512 uint4 fragments,
//   fi = (((ks*2+slab)*4+mt)*32+lane); a0..a3 of m16n8k16:
//   a0={A[m0][k0],A[m0][k0+1]} a1={A[m1][..]} a2={A[m0][k0+8],[k0+9]} a3={A[m1][..]}
//   m0 = slab*64+mt*16+gid, m1 = m0+8, k0 = ks*16 + 2*tig (within chunk)
// B tile (chunk c, nblk of 8): 256 uint4 fragments (two nt-tiles per uint4),
//   fj = (((ks*2+wn)*2+ntp)*32+lane); words
//   {b0(nt=2ntp), b1(nt=2ntp), b0(nt=2ntp+1), b1(nt=2ntp+1)},
//   b0(nt)={B[k0][n],B[k0+1][n]}, b1(nt)={B[k0+8][n],B[k0+9][n]},
//   n = nblk*64 + wn*32 + nt*8 + gid, k0 = ks*16 + 2*tig (within chunk)
__global__ void prep_kernel(const float* __restrict__ x,
                            const float* __restrict__ w,
                            const int*   __restrict__ idx) {
    const int c  = blockIdx.x;
    const int by = blockIdx.y;
    const int t  = threadIdx.x;

    if (by >= MTILES) {
        // ---- B pack ----
        const int nblk = by - MTILES;
        uint4* dst = g_bh + (size_t)(c * NBLKS + nblk) * 256;
        #pragma unroll
        for (int fi = t; fi < 256; fi += PTHREADS) {
            int lane = fi & 31;
            int ntp  = (fi >> 5) & 1;
            int wn   = (fi >> 6) & 1;
            int ks   = (fi >> 7) & 1;
            int gid  = lane >> 2, tig = lane & 3;

            int n0 = nblk * 64 + wn * 32 + (2 * ntp) * 8 + gid;
            int k  = c * BK + ks * 16 + tig * 2;
            const float* wp = w + (size_t)k * N_TOTAL + n0;
            uint4 o;
            o.x = h2(wp[0],               wp[N_TOTAL]);
            o.y = h2(wp[8 * N_TOTAL],     wp[9 * N_TOTAL]);
            o.z = h2(wp[8],               wp[N_TOTAL + 8]);
            o.w = h2(wp[8 * N_TOTAL + 8], wp[9 * N_TOTAL + 8]);
            dst[fi] = o;
        }
        return;
    }

    // ---- A gather (scattered __ldg; sorted idx gives L1 locality) ----
    __shared__ int skoff[BK];
    __shared__ int smb[128];
    const int bmt = by;

    if (t < BK) {
        int v  = idx[c * BK + t];
        int ch = v / 9;
        int rs = v - ch * 9;
        skoff[t] = ch * 1024 + (rs / 3) * 32 + (rs % 3);
    }
    if (t < 128) {
        int m = bmt * 128 + t;
        if (m >= M_TOTAL) m = 0;
        int nb  = m / OHW;
        int rem = m - nb * OHW;
        smb[t] = nb * XSTRIDE_N + (rem / 30) * 32 + (rem % 30);
    }
    __syncthreads();

    uint4* dst = g_ah + (size_t)(c * MTILES + bmt) * 512;
    #pragma unroll
    for (int fi = t; fi < 512; fi += PTHREADS) {
        int lane = fi & 31;
        int mt   = (fi >> 5) & 3;
        int slab = (fi >> 7) & 1;
        int ks   = (fi >> 8) & 1;
        int gid  = lane >> 2, tig = lane & 3;

        int mrow = slab * 64 + mt * 16 + gid;
        int mb0  = smb[mrow];
        int mb1  = smb[mrow + 8];
        int kb   = ks * 16 + tig * 2;
        int ko0 = skoff[kb],     ko1 = skoff[kb + 1];
        int ko8 = skoff[kb + 8], ko9 = skoff[kb + 9];

        uint4 o;
        o.x = h2(__ldg(x + mb0 + ko0), __ldg(x + mb0 + ko1));
        o.y = h2(__ldg(x + mb1 + ko0), __ldg(x + mb1 + ko1));
        o.z = h2(__ldg(x + mb0 + ko8), __ldg(x + mb0 + ko9));
        o.w = h2(__ldg(x + mb1 + ko8), __ldg(x + mb1 + ko9));
        dst[fi] = o;
    }
}

// ---------------- main: 64x64 CTA, m32n32 warps, A double-buffered, B just-in-time ----------------
__global__ __launch_bounds__(NTHREADS, 7)
void masked_conv_main(float* __restrict__ out)
{
    const int t  = threadIdx.x;
    const int bn = blockIdx.x;   // fast dim -> A hot in L1/L2 across bn
    const int bm = blockIdx.y;   // 0..224 (64-row tiles; exact, no bounds checks)

    const int lane   = t & 31;
    const int wid    = t >> 5;
    const int warp_m = wid >> 1;    // 2 x 32-row halves
    const int warp_n = wid & 1;     // 2 x 32-col halves
    const int gid    = lane >> 2;
    const int tig    = lane & 3;

    float acc[2][4][4];
    #pragma unroll
    for (int a = 0; a < 2; a++)
        #pragma unroll
        for (int b = 0; b < 4; b++)
            #pragma unroll
            for (int c = 0; c < 4; c++)
                acc[a][b][c] = 0.0f;

    // A: 128-tile (bm>>1), slab (bm&1), rows warp_m*32 .. +31
    const uint4* pa0 = g_ah + (size_t)(bm >> 1) * 512
                       + (bm & 1) * 128 + warp_m * 64 + lane;
    // B: (bn, warp_n) half (L1/L2-hot: shared by all 225 bm-CTAs)
    const uint4* pb0 = g_bh + (size_t)bn * 256 + warp_n * 64 + lane;

    uint4 Af[2][2];   // double-buffered A (long-latency stream)

    auto load_a = [&](int s, int buf) {
        int c  = s >> 1;
        int ks = s & 1;
        const uint4* pa = pa0 + (size_t)c * (MTILES * 512) + ks * 256;
        Af[buf][0] = __ldg(pa);
        Af[buf][1] = __ldg(pa + 32);
    };

    load_a(0, 0);
    int cur = 0;
    #pragma unroll 1
    for (int s = 0; s < NSTEPS; s++) {
        int c  = s >> 1;
        int ks = s & 1;
        // B just-in-time (cache-hot)
        const uint4* pb = pb0 + (size_t)c * (NBLKS * 256) + ks * 128;
        uint4 Bf0 = __ldg(pb);
        uint4 Bf1 = __ldg(pb + 32);
        // prefetch next A
        if (s + 1 < NSTEPS) load_a(s + 1, cur ^ 1);

        const uint4 Bfr[2] = {Bf0, Bf1};
        #pragma unroll
        for (int mt = 0; mt < 2; mt++)
            #pragma unroll
            for (int nt = 0; nt < 4; nt++) {
                uint32_t b0 = (nt & 1) ? Bfr[nt >> 1].z : Bfr[nt >> 1].x;
                uint32_t b1 = (nt & 1) ? Bfr[nt >> 1].w : Bfr[nt >> 1].y;
                asm volatile(
                    "mma.sync.aligned.m16n8k16.row.col.f32.f16.f16.f32 "
                    "{%0,%1,%2,%3}, {%4,%5,%6,%7}, {%8,%9}, {%0,%1,%2,%3};\n"
                    : "+f"(acc[mt][nt][0]), "+f"(acc[mt][nt][1]),
                      "+f"(acc[mt][nt][2]), "+f"(acc[mt][nt][3])
                    : "r"(Af[cur][mt].x), "r"(Af[cur][mt].y),
                      "r"(Af[cur][mt].z), "r"(Af[cur][mt].w),
                      "r"(b0), "r"(b1));
            }
        cur ^= 1;
    }

    // ---- epilogue (no bounds checks: 225*64 == M_TOTAL) ----
    #pragma unroll
    for (int mt = 0; mt < 2; mt++) {
        int m0 = bm * 64 + warp_m * 32 + mt * 16 + gid;
        int m1 = m0 + 8;
        int nb0 = m0 / OHW, p0 = m0 - nb0 * OHW;
        int nb1 = m1 / OHW, p1 = m1 - nb1 * OHW;
        int base0 = nb0 * OSTRIDE_N + p0;
        int base1 = nb1 * OSTRIDE_N + p1;
        #pragma unroll
        for (int nt = 0; nt < 4; nt++) {
            int oc = bn * 64 + warp_n * 32 + nt * 8 + tig * 2;
            out[base0 + oc * OHW]       = acc[mt][nt][0];
            out[base0 + (oc + 1) * OHW] = acc[mt][nt][1];
            out[base1 + oc * OHW]       = acc[mt][nt][2];
            out[base1 + (oc + 1) * OHW] = acc[mt][nt][3];
        }
    }
}

// ---------------- launch ----------------
extern "C" void kernel_launch(void* const* d_in, const int* in_sizes, int n_in,
                              void* d_out, int out_size) {
    const float* x   = (const float*)d_in[0];   // (16,256,32,32) fp32
    const float* w   = (const float*)d_in[1];   // (1152,512) fp32
    const int*   idx = (const int*)d_in[2];     // (1152,) int32 sorted
    float*       out = (float*)d_out;           // (16,512,30,30) fp32

    prep_kernel<<<dim3(NCHUNK, MTILES + NBLKS), PTHREADS>>>(x, w, idx);

    dim3 grid(NBLKS, M64TILES);                 // (8, 225) = 1800 CTAs
    masked_conv_main<<<grid, NTHREADS>>>(out);
}

// round 17
// speedup vs baseline: 1.9810x; 1.9810x over previous
#include <cuda_runtime.h>
#include <cuda_fp16.h>
#include <cstdint>

// ---------------- problem constants ----------------
#define M_TOTAL   14400      // 16 * 30 * 30
#define N_TOTAL   512
#define K_TOTAL   1152
#define OHW       900        // 30*30
#define XSTRIDE_N 262144     // 256*32*32
#define OSTRIDE_N 460800     // 512*900

#define BK 32
#define NCHUNK   36          // K_TOTAL / BK
#define NSTEPS   72          // 2 ks-steps per chunk
#define MTILES   113         // prep A granularity stays 128 rows
#define M64TILES 225         // 14400 / 64 exactly
#define NBLKS    8           // N_TOTAL / 64
#define PTHREADS 256
#define NTHREADS 128

__device__ uint4 g_ah[NCHUNK * MTILES * 512];   // ~33.3 MB, per-thread A fragments
__device__ uint4 g_bh[NCHUNK * NBLKS * 256];    // ~1.2 MB,  B fragments (uint4-packed)

// pack two floats into f16x2 word: lo = a, hi = b
__device__ __forceinline__ uint32_t h2(float a, float b) {
    uint32_t r;
    asm("cvt.rn.f16x2.f32 %0, %1, %2;" : "=r"(r) : "f"(b), "f"(a));
    return r;
}

// ---------------- fused prep: A gather (by<113) or B pack (by>=113) ----------------
__global__ void prep_kernel(const float* __restrict__ x,
                            const float* __restrict__ w,
                            const int*   __restrict__ idx) {
    const int c  = blockIdx.x;
    const int by = blockIdx.y;
    const int t  = threadIdx.x;

    if (by >= MTILES) {
        // ---- B pack ----
        const int nblk = by - MTILES;
        uint4* dst = g_bh + (size_t)(c * NBLKS + nblk) * 256;
        #pragma unroll
        for (int fi = t; fi < 256; fi += PTHREADS) {
            int lane = fi & 31;
            int ntp  = (fi >> 5) & 1;
            int wn   = (fi >> 6) & 1;
            int ks   = (fi >> 7) & 1;
            int gid  = lane >> 2, tig = lane & 3;

            int n0 = nblk * 64 + wn * 32 + (2 * ntp) * 8 + gid;
            int k  = c * BK + ks * 16 + tig * 2;
            const float* wp = w + (size_t)k * N_TOTAL + n0;
            uint4 o;
            o.x = h2(wp[0],               wp[N_TOTAL]);
            o.y = h2(wp[8 * N_TOTAL],     wp[9 * N_TOTAL]);
            o.z = h2(wp[8],               wp[N_TOTAL + 8]);
            o.w = h2(wp[8 * N_TOTAL + 8], wp[9 * N_TOTAL + 8]);
            dst[fi] = o;
        }
        return;
    }

    // ---- A gather (scattered __ldg; sorted idx gives L1 locality) ----
    __shared__ int skoff[BK];
    __shared__ int smb[128];
    const int bmt = by;

    if (t < BK) {
        int v  = idx[c * BK + t];
        int ch = v / 9;
        int rs = v - ch * 9;
        skoff[t] = ch * 1024 + (rs / 3) * 32 + (rs % 3);
    }
    if (t < 128) {
        int m = bmt * 128 + t;
        if (m >= M_TOTAL) m = 0;
        int nb  = m / OHW;
        int rem = m - nb * OHW;
        smb[t] = nb * XSTRIDE_N + (rem / 30) * 32 + (rem % 30);
    }
    __syncthreads();

    uint4* dst = g_ah + (size_t)(c * MTILES + bmt) * 512;
    #pragma unroll
    for (int fi = t; fi < 512; fi += PTHREADS) {
        int lane = fi & 31;
        int mt   = (fi >> 5) & 3;
        int slab = (fi >> 7) & 1;
        int ks   = (fi >> 8) & 1;
        int gid  = lane >> 2, tig = lane & 3;

        int mrow = slab * 64 + mt * 16 + gid;
        int mb0  = smb[mrow];
        int mb1  = smb[mrow + 8];
        int kb   = ks * 16 + tig * 2;
        int ko0 = skoff[kb],     ko1 = skoff[kb + 1];
        int ko8 = skoff[kb + 8], ko9 = skoff[kb + 9];

        uint4 o;
        o.x = h2(__ldg(x + mb0 + ko0), __ldg(x + mb0 + ko1));
        o.y = h2(__ldg(x + mb1 + ko0), __ldg(x + mb1 + ko1));
        o.z = h2(__ldg(x + mb0 + ko8), __ldg(x + mb0 + ko9));
        o.w = h2(__ldg(x + mb1 + ko8), __ldg(x + mb1 + ko9));
        dst[fi] = o;
    }
}

// ---------------- main: 64x64 CTA, m32n32 warps, double-buffered (R13 best) ----------------
__global__ __launch_bounds__(NTHREADS, 6)
void masked_conv_main(float* __restrict__ out)
{
    const int t  = threadIdx.x;
    const int bn = blockIdx.x;   // fast dim -> A hot in L1/L2 across bn
    const int bm = blockIdx.y;   // 0..224 (64-row tiles; exact, no bounds checks)

    const int lane   = t & 31;
    const int wid    = t >> 5;
    const int warp_m = wid >> 1;    // 2 x 32-row halves
    const int warp_n = wid & 1;     // 2 x 32-col halves
    const int gid    = lane >> 2;
    const int tig    = lane & 3;

    float acc[2][4][4];
    #pragma unroll
    for (int a = 0; a < 2; a++)
        #pragma unroll
        for (int b = 0; b < 4; b++)
            #pragma unroll
            for (int c = 0; c < 4; c++)
                acc[a][b][c] = 0.0f;

    // A: 128-tile (bm>>1), slab (bm&1), rows warp_m*32 .. +31
    const uint4* pa0 = g_ah + (size_t)(bm >> 1) * 512
                       + (bm & 1) * 128 + warp_m * 64 + lane;
    // B: (bn, warp_n) half
    const uint4* pb0 = g_bh + (size_t)bn * 256 + warp_n * 64 + lane;

    uint4 Af[2][2];
    uint4 Bf[2][2];

    auto load_step = [&](int s, int buf) {
        int c  = s >> 1;
        int ks = s & 1;
        const uint4* pa = pa0 + (size_t)c * (MTILES * 512) + ks * 256;
        Af[buf][0] = __ldg(pa);
        Af[buf][1] = __ldg(pa + 32);
        const uint4* pb = pb0 + (size_t)c * (NBLKS * 256) + ks * 128;
        Bf[buf][0] = __ldg(pb);
        Bf[buf][1] = __ldg(pb + 32);
    };

    auto compute = [&](int buf) {
        #pragma unroll
        for (int mt = 0; mt < 2; mt++)
            #pragma unroll
            for (int nt = 0; nt < 4; nt++) {
                uint32_t b0 = (nt & 1) ? Bf[buf][nt >> 1].z : Bf[buf][nt >> 1].x;
                uint32_t b1 = (nt & 1) ? Bf[buf][nt >> 1].w : Bf[buf][nt >> 1].y;
                asm volatile(
                    "mma.sync.aligned.m16n8k16.row.col.f32.f16.f16.f32 "
                    "{%0,%1,%2,%3}, {%4,%5,%6,%7}, {%8,%9}, {%0,%1,%2,%3};\n"
                    : "+f"(acc[mt][nt][0]), "+f"(acc[mt][nt][1]),
                      "+f"(acc[mt][nt][2]), "+f"(acc[mt][nt][3])
                    : "r"(Af[buf][mt].x), "r"(Af[buf][mt].y),
                      "r"(Af[buf][mt].z), "r"(Af[buf][mt].w),
                      "r"(b0), "r"(b1));
            }
    };

    load_step(0, 0);
    #pragma unroll 1
    for (int s = 0; s < NSTEPS; s += 2) {
        load_step(s + 1, 1);
        compute(0);
        if (s + 2 < NSTEPS) load_step(s + 2, 0);
        compute(1);
    }

    // ---- epilogue (no bounds checks: 225*64 == M_TOTAL) ----
    #pragma unroll
    for (int mt = 0; mt < 2; mt++) {
        int m0 = bm * 64 + warp_m * 32 + mt * 16 + gid;
        int m1 = m0 + 8;
        int nb0 = m0 / OHW, p0 = m0 - nb0 * OHW;
        int nb1 = m1 / OHW, p1 = m1 - nb1 * OHW;
        int base0 = nb0 * OSTRIDE_N + p0;
        int base1 = nb1 * OSTRIDE_N + p1;
        #pragma unroll
        for (int nt = 0; nt < 4; nt++) {
            int oc = bn * 64 + warp_n * 32 + nt * 8 + tig * 2;
            out[base0 + oc * OHW]       = acc[mt][nt][0];
            out[base0 + (oc + 1) * OHW] = acc[mt][nt][1];
            out[base1 + oc * OHW]       = acc[mt][nt][2];
            out[base1 + (oc + 1) * OHW] = acc[mt][nt][3];
        }
    }
}

// ---------------- launch ----------------
extern "C" void kernel_launch(void* const* d_in, const int* in_sizes, int n_in,
                              void* d_out, int out_size) {
    const float* x   = (const float*)d_in[0];   // (16,256,32,32) fp32
    const float* w   = (const float*)d_in[1];   // (1152,512) fp32
    const int*   idx = (const int*)d_in[2];     // (1152,) int32 sorted
    float*       out = (float*)d_out;           // (16,512,30,30) fp32

    static bool attr_set = false;
    if (!attr_set) {
        // main uses no smem: maximize L1 carveout for A/B stream caching
        cudaFuncSetAttribute(masked_conv_main,
                             cudaFuncAttributePreferredSharedMemoryCarveout, 0);
        attr_set = true;
    }

    prep_kernel<<<dim3(NCHUNK, MTILES + NBLKS), PTHREADS>>>(x, w, idx);

    dim3 grid(NBLKS, M64TILES);                 // (8, 225) = 1800 CTAs
    masked_conv_main<<<grid, NTHREADS>>>(out);
}